// round 4
// baseline (speedup 1.0000x reference)
#include <cuda_runtime.h>
#include <cuda_bf16.h>
#include <cstdint>

#define NUM_USERS 50000
#define NUM_ITEMS 40000
#define EMB 64
#define NNZ 2000000
#define BATCH 1024
#define INTMX 0x7FFFFFFF
#define MAXROW 2048

// ---- scratch (static __device__ globals; no allocation allowed) ----
__device__ float         g_WqT[NUM_ITEMS * 128];     // Wq transposed: [item][128]
__device__ __nv_bfloat16 g_Wpb[NUM_ITEMS * EMB];     // Wp in bf16:   [item][64]
__device__ float         g_hsel[BATCH * 128];        // selected-user h accumulators
__device__ int           g_map[NUM_USERS];           // user -> first batch slot
__device__ __nv_bfloat16 g_zb[BATCH * EMB];          // z in bf16
__device__ float         g_sexp[BATCH];
__device__ float         g_sdot[BATCH];
__device__ int           g_nzrow[BATCH];             // per-row nonzero count of x
__device__ int           g_nzlist[BATCH * MAXROW];   // per-row nonzero columns
__device__ float         g_kl;

__device__ __forceinline__ unsigned pack_bf162(float lo, float hi) {
    __nv_bfloat162 t = __floats2bfloat162_rn(lo, hi);
    return *(unsigned*)&t;
}

// ---- 0: zero scratch ----
__global__ void k_zero() {
    int i = blockIdx.x * blockDim.x + threadIdx.x;
    if (i < BATCH * 128) g_hsel[i] = 0.f;
    if (i < NUM_USERS)   g_map[i] = INTMX;
    if (i < BATCH) { g_sexp[i] = 0.f; g_sdot[i] = 0.f; g_nzrow[i] = 0; }
    if (i == 0) g_kl = 0.f;
}

// ---- 1: build user -> slot map ----
__global__ void k_map(const int* __restrict__ user) {
    int b = blockIdx.x * blockDim.x + threadIdx.x;
    if (b < BATCH) atomicMin(&g_map[user[b]], b);
}

// ---- 2: transpose Wq[128][40000] -> WqT[40000][128] ----
__global__ void k_transpose(const float* __restrict__ Wq) {
    __shared__ float tile[32][33];
    int i0 = blockIdx.x * 32, k0 = blockIdx.y * 32;
    int tx = threadIdx.x, ty = threadIdx.y;      // block (32,8)
#pragma unroll
    for (int r = 0; r < 32; r += 8)
        tile[ty + r][tx] = Wq[(size_t)(k0 + ty + r) * NUM_ITEMS + i0 + tx];
    __syncthreads();
#pragma unroll
    for (int r = 0; r < 32; r += 8)
        g_WqT[(size_t)(i0 + ty + r) * 128 + k0 + tx] = tile[tx][ty + r];
}

// ---- 3: Wp f32 -> bf16 (32B read / 16B write per thread) ----
__global__ void k_wpcvt(const float* __restrict__ Wp) {
    int i = blockIdx.x * blockDim.x + threadIdx.x;
    if (i < NUM_ITEMS * EMB / 8) {
        const float4* in4 = (const float4*)Wp;
        float4 a = in4[2 * i], b = in4[2 * i + 1];
        uint4 o;
        o.x = pack_bf162(a.x, a.y);
        o.y = pack_bf162(a.z, a.w);
        o.z = pack_bf162(b.x, b.y);
        o.w = pack_bf162(b.z, b.w);
        ((uint4*)g_Wpb)[i] = o;
    }
}

// ---- 4: scatter kept edges (warp-ballot compaction) ----
__global__ void k_edges(const float* __restrict__ vals,
                        const int* __restrict__ rows,
                        const int* __restrict__ cols) {
    int idx  = blockIdx.x * blockDim.x + threadIdx.x;
    int lane = threadIdx.x & 31;
    int slot = INTMX, col = 0;
    float val = 0.f;
    if (idx < NNZ) {
        slot = g_map[rows[idx]];
        col  = cols[idx];
        val  = vals[idx];
    }
    unsigned m = __ballot_sync(0xFFFFFFFFu, slot != INTMX);
    while (m) {
        int j = __ffs(m) - 1; m &= m - 1;
        int   c = __shfl_sync(0xFFFFFFFFu, col, j);
        float v = __shfl_sync(0xFFFFFFFFu, val, j);
        int   s = __shfl_sync(0xFFFFFFFFu, slot, j);
        const float* wr = &g_WqT[(size_t)c * 128];
        float* hr = &g_hsel[s * 128];
#pragma unroll
        for (int k = lane; k < 128; k += 32)
            atomicAdd(&hr[k], v * wr[k]);
    }
}

// ---- 5: reparameterize + KL ----
__global__ void k_z(const float* __restrict__ bq,
                    const float* __restrict__ eps,
                    const int* __restrict__ user) {
    int b = blockIdx.x, k = threadIdx.x;   // 64 threads
    int u = user[b];
    int s = g_map[u];
    float mu = g_hsel[s * 128 + k]      + bq[k];
    float lv = g_hsel[s * 128 + 64 + k] + bq[64 + k];
    float z  = mu + eps[u * EMB + k] * __expf(0.5f * lv);
    g_zb[b * EMB + k] = __float2bfloat16(z);
    float t = 1.f + lv - mu * mu - __expf(lv);
#pragma unroll
    for (int o = 16; o > 0; o >>= 1) t += __shfl_down_sync(0xFFFFFFFFu, t, o);
    __shared__ float sm[2];
    if ((threadIdx.x & 31) == 0) sm[threadIdx.x >> 5] = t;
    __syncthreads();
    if (threadIdx.x == 0) atomicAdd(&g_kl, sm[0] + sm[1]);
}

// ---- 6: stream x, compact nonzero columns per row (BW-bound) ----
// NOTE: loop trip count is uniform across the block so every lane stays
// active through the warp shuffles (10000 % 256 != 0 tail is predicated
// with v=0, NOT skipped — shuffles with exited lanes are UB).
__global__ void __launch_bounds__(256)
k_xscan(const float* __restrict__ x) {
    int b = blockIdx.x;
    int lane = threadIdx.x & 31;
    const float4* xr = (const float4*)(x + (size_t)b * NUM_ITEMS);
    int* list = &g_nzlist[b * MAXROW];
    const int NCHUNK = NUM_ITEMS / 4;               // 10000
    const int NITER  = (NCHUNK + 255) / 256;        // 40
    for (int it = 0; it < NITER; it++) {
        int i = it * 256 + threadIdx.x;
        float4 v = make_float4(0.f, 0.f, 0.f, 0.f);
        if (i < NCHUNK) v = xr[i];
        int k = (v.x != 0.f) + (v.y != 0.f) + (v.z != 0.f) + (v.w != 0.f);
        // inclusive warp scan of k (all 32 lanes active)
        int pfx = k;
#pragma unroll
        for (int o = 1; o < 32; o <<= 1) {
            int t = __shfl_up_sync(0xFFFFFFFFu, pfx, o);
            if (lane >= o) pfx += t;
        }
        int total = __shfl_sync(0xFFFFFFFFu, pfx, 31);
        if (total) {
            int base = 0;
            if (lane == 31) base = atomicAdd(&g_nzrow[b], total);
            base = __shfl_sync(0xFFFFFFFFu, base, 31);
            int off = base + pfx - k;
            int c = i * 4;
            if (v.x != 0.f && off < MAXROW) list[off++] = c;
            if (v.y != 0.f && off < MAXROW) list[off++] = c + 1;
            if (v.z != 0.f && off < MAXROW) list[off++] = c + 2;
            if (v.w != 0.f && off < MAXROW) list[off++] = c + 3;
        }
    }
}

// ---- 7: decoder GEMM (bf16 HMMA) + exp accumulation (compute-bound) ----
__device__ __forceinline__ void mma16816(float* d, const unsigned* a, const unsigned* b) {
    asm volatile(
        "mma.sync.aligned.m16n8k16.row.col.f32.bf16.bf16.f32 "
        "{%0,%1,%2,%3}, {%4,%5,%6,%7}, {%8,%9}, {%0,%1,%2,%3};\n"
        : "+f"(d[0]), "+f"(d[1]), "+f"(d[2]), "+f"(d[3])
        : "r"(a[0]), "r"(a[1]), "r"(a[2]), "r"(a[3]), "r"(b[0]), "r"(b[1]));
}

__global__ void __launch_bounds__(256)
k_gemm(const float* __restrict__ bp) {
    int w = threadIdx.x >> 5, lane = threadIdx.x & 31;
    int wm = w & 3, wn = w >> 2;                 // 4 warps along M, 2 along N
    int m_base = blockIdx.y * 128 + wm * 32;     // batch rows (in-range)
    int n_base = blockIdx.x * 128 + wn * 64;     // item cols (tail-predicated)
    int g = lane >> 2, tg = lane & 3;

    // A fragments: z tile 32(M) x 64(K), register-resident
    unsigned a[2][4][4];
#pragma unroll
    for (int mf = 0; mf < 2; mf++) {
        int r0 = m_base + mf * 16 + g;
#pragma unroll
        for (int kf = 0; kf < 4; kf++) {
            int kb = kf * 16 + tg * 2;
            a[mf][kf][0] = *(const unsigned*)&g_zb[(r0)     * 64 + kb];
            a[mf][kf][1] = *(const unsigned*)&g_zb[(r0 + 8) * 64 + kb];
            a[mf][kf][2] = *(const unsigned*)&g_zb[(r0)     * 64 + kb + 8];
            a[mf][kf][3] = *(const unsigned*)&g_zb[(r0 + 8) * 64 + kb + 8];
        }
    }

    float sexp[4] = {0, 0, 0, 0};

#pragma unroll
    for (int nf = 0; nf < 8; nf++) {
        int i0 = n_base + nf * 8;
        int ib = i0 + g;
        unsigned bf[4][2];
        if (ib < NUM_ITEMS) {
#pragma unroll
            for (int kf = 0; kf < 4; kf++) {
                bf[kf][0] = *(const unsigned*)&g_Wpb[(size_t)ib * 64 + kf * 16 + tg * 2];
                bf[kf][1] = *(const unsigned*)&g_Wpb[(size_t)ib * 64 + kf * 16 + tg * 2 + 8];
            }
        } else {
#pragma unroll
            for (int kf = 0; kf < 4; kf++) { bf[kf][0] = 0u; bf[kf][1] = 0u; }
        }
        float d[2][4] = {{0, 0, 0, 0}, {0, 0, 0, 0}};
#pragma unroll
        for (int mf = 0; mf < 2; mf++)
#pragma unroll
            for (int kf = 0; kf < 4; kf++)
                mma16816(d[mf], a[mf][kf], bf[kf]);

        int c0 = i0 + tg * 2;
        if (c0 < NUM_ITEMS) {
            float2 bpv = *(const float2*)&bp[c0];
#pragma unroll
            for (int mf = 0; mf < 2; mf++)
#pragma unroll
                for (int h = 0; h < 2; h++) {
                    float v0 = d[mf][h * 2 + 0] + bpv.x;
                    float v1 = d[mf][h * 2 + 1] + bpv.y;
                    sexp[mf * 2 + h] += __expf(v0) + __expf(v1);
                }
        }
    }

#pragma unroll
    for (int li = 0; li < 4; li++) {
        float se = sexp[li];
#pragma unroll
        for (int o = 1; o < 4; o <<= 1)
            se += __shfl_xor_sync(0xFFFFFFFFu, se, o);
        if (tg == 0) {
            int row = m_base + (li >> 1) * 16 + (li & 1) * 8 + g;
            atomicAdd(&g_sexp[row], se);
        }
    }
}

// ---- 8: per-row sparse dot  sdot_b = z_b . (sum_j Wp[c_j]) + sum_j bp[c_j] ----
__global__ void __launch_bounds__(256)
k_sdot(const float* __restrict__ bp) {
    int b = blockIdx.x;
    int w = threadIdx.x >> 5, lane = threadIdx.x & 31;
    int n = g_nzrow[b];
    if (n > MAXROW) n = MAXROW;
    const int* list = &g_nzlist[b * MAXROW];

    // this lane's z slice (k = 2*lane, 2*lane+1)
    unsigned zr = ((const unsigned*)&g_zb[b * EMB])[lane];
    __nv_bfloat162 zb2 = *(__nv_bfloat162*)&zr;
    float2 z = make_float2(__bfloat162float(__low2bfloat16(zb2)),
                           __bfloat162float(__high2bfloat16(zb2)));

    float2 accW = make_float2(0.f, 0.f);
    float accB = 0.f;
    for (int j = w; j < n; j += 8) {
        int c = list[j];                          // broadcast load (same j all lanes)
        unsigned wv = ((const unsigned*)&g_Wpb[(size_t)c * EMB])[lane];  // coalesced 128B
        __nv_bfloat162 wb2 = *(__nv_bfloat162*)&wv;
        accW.x += __bfloat162float(__low2bfloat16(wb2));
        accW.y += __bfloat162float(__high2bfloat16(wb2));
        if (lane == 0) accB += bp[c];
    }
    float part = accW.x * z.x + accW.y * z.y + accB;
#pragma unroll
    for (int o = 16; o > 0; o >>= 1) part += __shfl_down_sync(0xFFFFFFFFu, part, o);
    __shared__ float sm[8];
    if (lane == 0) sm[w] = part;
    __syncthreads();
    if (threadIdx.x == 0) {
        float s = 0.f;
#pragma unroll
        for (int i = 0; i < 8; i++) s += sm[i];
        g_sdot[b] = s;
    }
}

// ---- 9: final reduction ----
__global__ void k_final(float* __restrict__ out) {
    __shared__ float sm[256];
    float acc = 0.f;
    for (int r = threadIdx.x; r < BATCH; r += 256)
        acc += (float)g_nzrow[r] * logf(g_sexp[r]) - g_sdot[r];
    sm[threadIdx.x] = acc;
    __syncthreads();
    for (int o = 128; o > 0; o >>= 1) {
        if (threadIdx.x < o) sm[threadIdx.x] += sm[threadIdx.x + o];
        __syncthreads();
    }
    if (threadIdx.x == 0) {
        out[0] = sm[0] / (float)BATCH;
        out[1] = -0.5f * g_kl / (float)BATCH;
    }
}

extern "C" void kernel_launch(void* const* d_in, const int* in_sizes, int n_in,
                              void* d_out, int out_size) {
    const float* graph_vals = (const float*)d_in[0];
    const float* Wq         = (const float*)d_in[1];
    const float* bq         = (const float*)d_in[2];
    const float* Wp         = (const float*)d_in[3];
    const float* bp         = (const float*)d_in[4];
    const float* x          = (const float*)d_in[5];
    const float* eps        = (const float*)d_in[6];
    const int*   graph_rows = (const int*)d_in[7];
    const int*   graph_cols = (const int*)d_in[8];
    const int*   user       = (const int*)d_in[9];
    float* out = (float*)d_out;

    k_zero<<<512, 256>>>();
    k_map<<<4, 256>>>(user);
    {
        dim3 grid(NUM_ITEMS / 32, 128 / 32);
        dim3 blk(32, 8);
        k_transpose<<<grid, blk>>>(Wq);
    }
    k_wpcvt<<<(NUM_ITEMS * EMB / 8 + 255) / 256, 256>>>(Wp);
    k_edges<<<(NNZ + 255) / 256, 256>>>(graph_vals, graph_rows, graph_cols);
    k_z<<<BATCH, 64>>>(bq, eps, user);
    k_xscan<<<BATCH, 256>>>(x);
    {
        dim3 grid((NUM_ITEMS + 127) / 128, BATCH / 128);
        k_gemm<<<grid, 256>>>(bp);
    }
    k_sdot<<<BATCH, 256>>>(bp);
    k_final<<<1, 256>>>(out);
}

// round 5
// speedup vs baseline: 1.4715x; 1.4715x over previous
#include <cuda_runtime.h>
#include <cuda_bf16.h>
#include <cstdint>

#define NUM_USERS 50000
#define NUM_ITEMS 40000
#define EMB 64
#define NNZ 2000000
#define BATCH 1024

// ---- scratch (static __device__ globals; no allocation allowed) ----
__device__ float         g_WqT[NUM_ITEMS * 128];     // Wq transposed: [item][128]
__device__ __nv_bfloat16 g_Wpb[NUM_ITEMS * EMB];     // Wp in bf16:   [item][64]
__device__ float         g_hsel[BATCH * 128];        // selected-user h accumulators
__device__ int           g_map[NUM_USERS];           // user -> batch slot (validated by back-check)
__device__ __nv_bfloat16 g_zb[BATCH * EMB];          // z in bf16
__device__ float         g_sexp[BATCH];
__device__ float         g_sdot[BATCH];
__device__ float         g_scnt[BATCH];
__device__ float         g_kl;

__device__ __forceinline__ unsigned pack_bf162(float lo, float hi) {
    __nv_bfloat162 t = __floats2bfloat162_rn(lo, hi);
    return *(unsigned*)&t;
}

// ---- 1: fused prep: Wq transpose + Wp->bf16 + zero scratch + user map ----
// grid layout: [0,5000) transpose tiles, [5000,6250) wpcvt, [6250,6762) hsel zero,
//              6762: misc zero + map stores
__global__ void __launch_bounds__(256)
k_prep(const float* __restrict__ Wq, const float* __restrict__ Wp,
       const int* __restrict__ user) {
    __shared__ float tile[32][33];
    int bid = blockIdx.x, tid = threadIdx.x;
    if (bid < 5000) {
        int i0 = (bid % 1250) * 32, k0 = (bid / 1250) * 32;
        int tx = tid & 31, ty = tid >> 5;          // (32,8)
#pragma unroll
        for (int r = 0; r < 32; r += 8)
            tile[ty + r][tx] = Wq[(size_t)(k0 + ty + r) * NUM_ITEMS + i0 + tx];
        __syncthreads();
#pragma unroll
        for (int r = 0; r < 32; r += 8)
            g_WqT[(size_t)(i0 + ty + r) * 128 + k0 + tx] = tile[tx][ty + r];
    } else if (bid < 6250) {
        int i = (bid - 5000) * 256 + tid;          // < 320000 exactly
        const float4* in4 = (const float4*)Wp;
        float4 a = in4[2 * i], b = in4[2 * i + 1];
        uint4 o;
        o.x = pack_bf162(a.x, a.y);
        o.y = pack_bf162(a.z, a.w);
        o.z = pack_bf162(b.x, b.y);
        o.w = pack_bf162(b.z, b.w);
        ((uint4*)g_Wpb)[i] = o;
    } else if (bid < 6762) {
        int i = (bid - 6250) * 256 + tid;          // < 131072 exactly
        g_hsel[i] = 0.f;
    } else {
#pragma unroll
        for (int b = tid; b < BATCH; b += 256) {
            g_sexp[b] = 0.f; g_sdot[b] = 0.f; g_scnt[b] = 0.f;
            g_map[user[b]] = b;                    // racing store; any winner valid
        }
        if (tid == 0) g_kl = 0.f;
    }
}

// ---- 2: scatter kept edges (warp-ballot compaction; map validated by back-check) ----
__global__ void k_edges(const float* __restrict__ vals,
                        const int* __restrict__ rows,
                        const int* __restrict__ cols,
                        const int* __restrict__ user) {
    int idx  = blockIdx.x * blockDim.x + threadIdx.x;
    int lane = threadIdx.x & 31;
    int slot = -1, col = 0;
    float val = 0.f;
    if (idx < NNZ) {
        int r = rows[idx];
        int s = g_map[r];
        if ((unsigned)s < BATCH && __ldg(&user[s]) == r) slot = s;
        col = cols[idx];
        val = vals[idx];
    }
    unsigned m = __ballot_sync(0xFFFFFFFFu, slot >= 0);
    while (m) {
        int j = __ffs(m) - 1; m &= m - 1;
        int   c = __shfl_sync(0xFFFFFFFFu, col, j);
        float v = __shfl_sync(0xFFFFFFFFu, val, j);
        int   s = __shfl_sync(0xFFFFFFFFu, slot, j);
        const float* wr = &g_WqT[(size_t)c * 128];
        float* hr = &g_hsel[s * 128];
#pragma unroll
        for (int k = lane; k < 128; k += 32)
            atomicAdd(&hr[k], v * wr[k]);
    }
}

// ---- 3: reparameterize + KL ----
__global__ void k_z(const float* __restrict__ bq,
                    const float* __restrict__ eps,
                    const int* __restrict__ user) {
    int b = blockIdx.x, k = threadIdx.x;   // 64 threads
    int u = user[b];
    int s = g_map[u];
    float mu = g_hsel[s * 128 + k]      + bq[k];
    float lv = g_hsel[s * 128 + 64 + k] + bq[64 + k];
    float z  = mu + eps[u * EMB + k] * __expf(0.5f * lv);
    g_zb[b * EMB + k] = __float2bfloat16(z);
    float t = 1.f + lv - mu * mu - __expf(lv);
#pragma unroll
    for (int o = 16; o > 0; o >>= 1) t += __shfl_down_sync(0xFFFFFFFFu, t, o);
    __shared__ float sm[2];
    if ((threadIdx.x & 31) == 0) sm[threadIdx.x >> 5] = t;
    __syncthreads();
    if (threadIdx.x == 0) atomicAdd(&g_kl, sm[0] + sm[1]);
}

// ---- 4: fused decoder GEMM (bf16 HMMA) + softmax-stats epilogue, software-pipelined ----
__device__ __forceinline__ void mma16816(float* d, const unsigned* a, const unsigned* b) {
    asm volatile(
        "mma.sync.aligned.m16n8k16.row.col.f32.bf16.bf16.f32 "
        "{%0,%1,%2,%3}, {%4,%5,%6,%7}, {%8,%9}, {%0,%1,%2,%3};\n"
        : "+f"(d[0]), "+f"(d[1]), "+f"(d[2]), "+f"(d[3])
        : "r"(a[0]), "r"(a[1]), "r"(a[2]), "r"(a[3]), "r"(b[0]), "r"(b[1]));
}

__global__ void __launch_bounds__(256)
k_gemm(const float* __restrict__ bp, const float* __restrict__ x) {
    int w = threadIdx.x >> 5, lane = threadIdx.x & 31;
    int wm = w & 3, wn = w >> 2;                 // 4 warps along M, 2 along N
    int m_base = blockIdx.y * 128 + wm * 32;     // batch rows (in-range)
    int n_base = blockIdx.x * 128 + wn * 64;     // item cols (tail-predicated)
    int g = lane >> 2, tg = lane & 3;

    // A fragments: z tile 32(M) x 64(K), register-resident
    unsigned a[2][4][4];
#pragma unroll
    for (int mf = 0; mf < 2; mf++) {
        int r0 = m_base + mf * 16 + g;
#pragma unroll
        for (int kf = 0; kf < 4; kf++) {
            int kb = kf * 16 + tg * 2;
            a[mf][kf][0] = *(const unsigned*)&g_zb[(r0)     * 64 + kb];
            a[mf][kf][1] = *(const unsigned*)&g_zb[(r0 + 8) * 64 + kb];
            a[mf][kf][2] = *(const unsigned*)&g_zb[(r0)     * 64 + kb + 8];
            a[mf][kf][3] = *(const unsigned*)&g_zb[(r0 + 8) * 64 + kb + 8];
        }
    }

    // x row base pointers for this thread's 4 result rows
    const float* xrow[4];
#pragma unroll
    for (int li = 0; li < 4; li++) {
        int row = m_base + (li >> 1) * 16 + (li & 1) * 8 + g;
        xrow[li] = x + (size_t)row * NUM_ITEMS;
    }

    float sexp[4] = {0, 0, 0, 0}, sdot[4] = {0, 0, 0, 0}, scnt[4] = {0, 0, 0, 0};

    unsigned bf[2][4][2];
    float2   xv[2][4];
    float2   bpv[2];

#define LOAD_STAGE(NF, BUF) do {                                               \
        int i0s = n_base + (NF) * 8;                                           \
        int ibs = i0s + g;                                                     \
        if (ibs < NUM_ITEMS) {                                                 \
            _Pragma("unroll")                                                  \
            for (int kf = 0; kf < 4; kf++) {                                   \
                bf[BUF][kf][0] = *(const unsigned*)&g_Wpb[(size_t)ibs * 64 + kf * 16 + tg * 2];     \
                bf[BUF][kf][1] = *(const unsigned*)&g_Wpb[(size_t)ibs * 64 + kf * 16 + tg * 2 + 8]; \
            }                                                                  \
        } else {                                                               \
            _Pragma("unroll")                                                  \
            for (int kf = 0; kf < 4; kf++) { bf[BUF][kf][0] = 0u; bf[BUF][kf][1] = 0u; } \
        }                                                                      \
        int c0s = i0s + tg * 2;                                                \
        if (c0s < NUM_ITEMS) {                                                 \
            bpv[BUF] = *(const float2*)&bp[c0s];                               \
            _Pragma("unroll")                                                  \
            for (int li = 0; li < 4; li++)                                     \
                xv[BUF][li] = __ldcs((const float2*)&xrow[li][c0s]);           \
        } else {                                                               \
            bpv[BUF] = make_float2(0.f, 0.f);                                  \
            _Pragma("unroll")                                                  \
            for (int li = 0; li < 4; li++) xv[BUF][li] = make_float2(0.f, 0.f);\
        }                                                                      \
    } while (0)

    LOAD_STAGE(0, 0);

#pragma unroll
    for (int nf = 0; nf < 8; nf++) {
        int buf = nf & 1;
        if (nf < 7) LOAD_STAGE(nf + 1, buf ^ 1);   // prefetch next stage

        float d[2][4] = {{0, 0, 0, 0}, {0, 0, 0, 0}};
#pragma unroll
        for (int mf = 0; mf < 2; mf++)
#pragma unroll
            for (int kf = 0; kf < 4; kf++)
                mma16816(d[mf], a[mf][kf], bf[buf][kf]);

        int c0 = n_base + nf * 8 + tg * 2;
        if (c0 < NUM_ITEMS) {
#pragma unroll
            for (int mf = 0; mf < 2; mf++)
#pragma unroll
                for (int h = 0; h < 2; h++) {
                    int li = mf * 2 + h;
                    float v0 = d[mf][h * 2 + 0] + bpv[buf].x;
                    float v1 = d[mf][h * 2 + 1] + bpv[buf].y;
                    sexp[li] += __expf(v0) + __expf(v1);
                    float2 xvv = xv[buf][li];
                    sdot[li] += xvv.x * v0 + xvv.y * v1;
                    scnt[li] += xvv.x + xvv.y;
                }
        }
    }
#undef LOAD_STAGE

    // reduce across the 4 threads of each group (tg), then atomics per row
#pragma unroll
    for (int li = 0; li < 4; li++) {
        float se = sexp[li], sd = sdot[li], sc = scnt[li];
#pragma unroll
        for (int o = 1; o < 4; o <<= 1) {
            se += __shfl_xor_sync(0xFFFFFFFFu, se, o);
            sd += __shfl_xor_sync(0xFFFFFFFFu, sd, o);
            sc += __shfl_xor_sync(0xFFFFFFFFu, sc, o);
        }
        if (tg == 0) {
            int row = m_base + (li >> 1) * 16 + (li & 1) * 8 + g;
            atomicAdd(&g_sexp[row], se);
            atomicAdd(&g_sdot[row], sd);
            atomicAdd(&g_scnt[row], sc);
        }
    }
}

// ---- 5: final reduction ----
__global__ void k_final(float* __restrict__ out) {
    __shared__ float sm[256];
    float acc = 0.f;
    for (int r = threadIdx.x; r < BATCH; r += 256)
        acc += g_scnt[r] * logf(g_sexp[r]) - g_sdot[r];
    sm[threadIdx.x] = acc;
    __syncthreads();
    for (int o = 128; o > 0; o >>= 1) {
        if (threadIdx.x < o) sm[threadIdx.x] += sm[threadIdx.x + o];
        __syncthreads();
    }
    if (threadIdx.x == 0) {
        out[0] = sm[0] / (float)BATCH;
        out[1] = -0.5f * g_kl / (float)BATCH;
    }
}

extern "C" void kernel_launch(void* const* d_in, const int* in_sizes, int n_in,
                              void* d_out, int out_size) {
    const float* graph_vals = (const float*)d_in[0];
    const float* Wq         = (const float*)d_in[1];
    const float* bq         = (const float*)d_in[2];
    const float* Wp         = (const float*)d_in[3];
    const float* bp         = (const float*)d_in[4];
    const float* x          = (const float*)d_in[5];
    const float* eps        = (const float*)d_in[6];
    const int*   graph_rows = (const int*)d_in[7];
    const int*   graph_cols = (const int*)d_in[8];
    const int*   user       = (const int*)d_in[9];
    float* out = (float*)d_out;

    k_prep<<<6763, 256>>>(Wq, Wp, user);
    k_edges<<<(NNZ + 255) / 256, 256>>>(graph_vals, graph_rows, graph_cols, user);
    k_z<<<BATCH, 64>>>(bq, eps, user);
    {
        dim3 grid((NUM_ITEMS + 127) / 128, BATCH / 128);
        k_gemm<<<grid, 256>>>(bp, x);
    }
    k_final<<<1, 256>>>(out);
}

// round 6
// speedup vs baseline: 1.6306x; 1.1081x over previous
#include <cuda_runtime.h>
#include <cuda_bf16.h>
#include <cstdint>

#define NUM_USERS 50000
#define NUM_ITEMS 40000
#define EMB 64
#define NNZ 2000000
#define BATCH 1024

// ---- scratch (static __device__ globals; no allocation allowed) ----
__device__ float         g_WqT[NUM_ITEMS * 128];     // Wq transposed: [item][128]
__device__ __nv_bfloat16 g_Wpb[NUM_ITEMS * EMB];     // Wp in bf16:   [item][64]
__device__ float         g_hsel[BATCH * 128];        // selected-user h accumulators
__device__ int           g_map[NUM_USERS];           // user -> batch slot (validated by back-check)
__device__ __nv_bfloat16 g_zb[BATCH * EMB];          // z in bf16
__device__ float         g_sexp[BATCH];
__device__ float         g_sdot[BATCH];
__device__ float         g_scnt[BATCH];
__device__ float         g_kl;

__device__ __forceinline__ unsigned pack_bf162(float lo, float hi) {
    __nv_bfloat162 t = __floats2bfloat162_rn(lo, hi);
    return *(unsigned*)&t;
}

// ---- 1: fused prep: Wq transpose + Wp->bf16 + zero scratch + user map ----
__global__ void __launch_bounds__(256)
k_prep(const float* __restrict__ Wq, const float* __restrict__ Wp,
       const int* __restrict__ user) {
    __shared__ float tile[32][33];
    int bid = blockIdx.x, tid = threadIdx.x;
    if (bid < 5000) {
        int i0 = (bid % 1250) * 32, k0 = (bid / 1250) * 32;
        int tx = tid & 31, ty = tid >> 5;          // (32,8)
#pragma unroll
        for (int r = 0; r < 32; r += 8)
            tile[ty + r][tx] = Wq[(size_t)(k0 + ty + r) * NUM_ITEMS + i0 + tx];
        __syncthreads();
#pragma unroll
        for (int r = 0; r < 32; r += 8)
            g_WqT[(size_t)(i0 + ty + r) * 128 + k0 + tx] = tile[tx][ty + r];
    } else if (bid < 6250) {
        int i = (bid - 5000) * 256 + tid;          // < 320000 exactly
        const float4* in4 = (const float4*)Wp;
        float4 a = in4[2 * i], b = in4[2 * i + 1];
        uint4 o;
        o.x = pack_bf162(a.x, a.y);
        o.y = pack_bf162(a.z, a.w);
        o.z = pack_bf162(b.x, b.y);
        o.w = pack_bf162(b.z, b.w);
        ((uint4*)g_Wpb)[i] = o;
    } else if (bid < 6762) {
        int i = (bid - 6250) * 256 + tid;          // < 131072 exactly
        g_hsel[i] = 0.f;
    } else {
#pragma unroll
        for (int b = tid; b < BATCH; b += 256) {
            g_sexp[b] = 0.f; g_sdot[b] = 0.f; g_scnt[b] = 0.f;
            g_map[user[b]] = b;                    // racing store; any winner valid
        }
        if (tid == 0) g_kl = 0.f;
    }
}

// ---- 2: scatter kept edges (warp-ballot compaction; map validated by back-check) ----
__global__ void k_edges(const float* __restrict__ vals,
                        const int* __restrict__ rows,
                        const int* __restrict__ cols,
                        const int* __restrict__ user) {
    int idx  = blockIdx.x * blockDim.x + threadIdx.x;
    int lane = threadIdx.x & 31;
    int slot = -1, col = 0;
    float val = 0.f;
    if (idx < NNZ) {
        int r = rows[idx];
        int s = g_map[r];
        if ((unsigned)s < BATCH && __ldg(&user[s]) == r) slot = s;
        col = cols[idx];
        val = vals[idx];
    }
    unsigned m = __ballot_sync(0xFFFFFFFFu, slot >= 0);
    while (m) {
        int j = __ffs(m) - 1; m &= m - 1;
        int   c = __shfl_sync(0xFFFFFFFFu, col, j);
        float v = __shfl_sync(0xFFFFFFFFu, val, j);
        int   s = __shfl_sync(0xFFFFFFFFu, slot, j);
        const float* wr = &g_WqT[(size_t)c * 128];
        float* hr = &g_hsel[s * 128];
#pragma unroll
        for (int k = lane; k < 128; k += 32)
            atomicAdd(&hr[k], v * wr[k]);
    }
}

// ---- 3: reparameterize + KL ----
__global__ void k_z(const float* __restrict__ bq,
                    const float* __restrict__ eps,
                    const int* __restrict__ user) {
    int b = blockIdx.x, k = threadIdx.x;   // 64 threads
    int u = user[b];
    int s = g_map[u];
    float mu = g_hsel[s * 128 + k]      + bq[k];
    float lv = g_hsel[s * 128 + 64 + k] + bq[64 + k];
    float z  = mu + eps[u * EMB + k] * __expf(0.5f * lv);
    g_zb[b * EMB + k] = __float2bfloat16(z);
    float t = 1.f + lv - mu * mu - __expf(lv);
#pragma unroll
    for (int o = 16; o > 0; o >>= 1) t += __shfl_down_sync(0xFFFFFFFFu, t, o);
    __shared__ float sm[2];
    if ((threadIdx.x & 31) == 0) sm[threadIdx.x >> 5] = t;
    __syncthreads();
    if (threadIdx.x == 0) atomicAdd(&g_kl, sm[0] + sm[1]);
}

// ---- 4: fused decoder GEMM (bf16 HMMA) + softmax-stats epilogue ----
// Wpb tile staged in smem (conflict-free 144B row stride); x double-buffered.
__device__ __forceinline__ void mma16816(float* d, const unsigned* a, const unsigned* b) {
    asm volatile(
        "mma.sync.aligned.m16n8k16.row.col.f32.bf16.bf16.f32 "
        "{%0,%1,%2,%3}, {%4,%5,%6,%7}, {%8,%9}, {%0,%1,%2,%3};\n"
        : "+f"(d[0]), "+f"(d[1]), "+f"(d[2]), "+f"(d[3])
        : "r"(a[0]), "r"(a[1]), "r"(a[2]), "r"(a[3]), "r"(b[0]), "r"(b[1]));
}

#define WP_STRIDE 144   // bytes per smem row: 128 data + 16 pad (bank-conflict-free)

__global__ void __launch_bounds__(256, 2)
k_gemm(const float* __restrict__ bp, const float* __restrict__ x) {
    __shared__ __align__(16) unsigned char sWp[128 * WP_STRIDE];   // 18 KB

    int w = threadIdx.x >> 5, lane = threadIdx.x & 31;
    int wm = w & 3, wn = w >> 2;                 // 4 warps along M, 2 along N
    int m_base = blockIdx.y * 128 + wm * 32;     // batch rows (in-range)
    int n_blk  = blockIdx.x * 128;
    int n_base = n_blk + wn * 64;                // item cols (tail-predicated)
    int g = lane >> 2, tg = lane & 3;

    // ---- fill smem Wpb tile: rows n_blk..n_blk+127, uint4-coalesced ----
#pragma unroll
    for (int it = 0; it < 4; it++) {
        int i = it * 256 + threadIdx.x;          // 0..1023
        int row = i >> 3, off = i & 7;
        int gr = n_blk + row;
        uint4 v = make_uint4(0u, 0u, 0u, 0u);
        if (gr < NUM_ITEMS) v = *(const uint4*)&g_Wpb[(size_t)gr * 64 + off * 8];
        *(uint4*)&sWp[row * WP_STRIDE + off * 16] = v;
    }
    __syncthreads();

    // ---- A fragments: z tile 32(M) x 64(K), register-resident ----
    unsigned a[2][4][4];
#pragma unroll
    for (int mf = 0; mf < 2; mf++) {
        int r0 = m_base + mf * 16 + g;
#pragma unroll
        for (int kf = 0; kf < 4; kf++) {
            int kb = kf * 16 + tg * 2;
            a[mf][kf][0] = *(const unsigned*)&g_zb[(r0)     * 64 + kb];
            a[mf][kf][1] = *(const unsigned*)&g_zb[(r0 + 8) * 64 + kb];
            a[mf][kf][2] = *(const unsigned*)&g_zb[(r0)     * 64 + kb + 8];
            a[mf][kf][3] = *(const unsigned*)&g_zb[(r0 + 8) * 64 + kb + 8];
        }
    }

    // x row base pointers for this thread's 4 result rows
    const float* xrow[4];
#pragma unroll
    for (int li = 0; li < 4; li++) {
        int row = m_base + (li >> 1) * 16 + (li & 1) * 8 + g;
        xrow[li] = x + (size_t)row * NUM_ITEMS;
    }

    float sexp[4] = {0, 0, 0, 0}, sdot[4] = {0, 0, 0, 0}, scnt[4] = {0, 0, 0, 0};

    float2 xv[2][4];
    float2 bpv[2];

#define LOAD_XBP(NF, BUF) do {                                                 \
        int c0s = n_base + (NF) * 8 + tg * 2;                                  \
        if (c0s < NUM_ITEMS) {                                                 \
            bpv[BUF] = *(const float2*)&bp[c0s];                               \
            _Pragma("unroll")                                                  \
            for (int li = 0; li < 4; li++)                                     \
                xv[BUF][li] = __ldcs((const float2*)&xrow[li][c0s]);           \
        } else {                                                               \
            bpv[BUF] = make_float2(0.f, 0.f);                                  \
            _Pragma("unroll")                                                  \
            for (int li = 0; li < 4; li++) xv[BUF][li] = make_float2(0.f, 0.f);\
        }                                                                      \
    } while (0)

    LOAD_XBP(0, 0);

#pragma unroll
    for (int nf = 0; nf < 8; nf++) {
        int buf = nf & 1;
        if (nf < 7) LOAD_XBP(nf + 1, buf ^ 1);   // prefetch next stage's x/bp

        // B fragments from smem (conflict-free LDS)
        int rloc = wn * 64 + nf * 8 + g;         // local smem row
        unsigned bf[4][2];
#pragma unroll
        for (int kf = 0; kf < 4; kf++) {
            bf[kf][0] = *(const unsigned*)&sWp[rloc * WP_STRIDE + kf * 32 + tg * 4];
            bf[kf][1] = *(const unsigned*)&sWp[rloc * WP_STRIDE + kf * 32 + tg * 4 + 16];
        }

        float d[2][4] = {{0, 0, 0, 0}, {0, 0, 0, 0}};
#pragma unroll
        for (int mf = 0; mf < 2; mf++)
#pragma unroll
            for (int kf = 0; kf < 4; kf++)
                mma16816(d[mf], a[mf][kf], bf[kf]);

        int c0 = n_base + nf * 8 + tg * 2;
        if (c0 < NUM_ITEMS) {
#pragma unroll
            for (int mf = 0; mf < 2; mf++)
#pragma unroll
                for (int h = 0; h < 2; h++) {
                    int li = mf * 2 + h;
                    float v0 = d[mf][h * 2 + 0] + bpv[buf].x;
                    float v1 = d[mf][h * 2 + 1] + bpv[buf].y;
                    sexp[li] += __expf(v0) + __expf(v1);
                    float2 xvv = xv[buf][li];
                    sdot[li] += xvv.x * v0 + xvv.y * v1;
                    scnt[li] += xvv.x + xvv.y;
                }
        }
    }
#undef LOAD_XBP

    // reduce across the 4 threads of each group (tg), then atomics per row
#pragma unroll
    for (int li = 0; li < 4; li++) {
        float se = sexp[li], sd = sdot[li], sc = scnt[li];
#pragma unroll
        for (int o = 1; o < 4; o <<= 1) {
            se += __shfl_xor_sync(0xFFFFFFFFu, se, o);
            sd += __shfl_xor_sync(0xFFFFFFFFu, sd, o);
            sc += __shfl_xor_sync(0xFFFFFFFFu, sc, o);
        }
        if (tg == 0) {
            int row = m_base + (li >> 1) * 16 + (li & 1) * 8 + g;
            atomicAdd(&g_sexp[row], se);
            atomicAdd(&g_sdot[row], sd);
            atomicAdd(&g_scnt[row], sc);
        }
    }
}

// ---- 5: final reduction ----
__global__ void k_final(float* __restrict__ out) {
    __shared__ float sm[256];
    float acc = 0.f;
    for (int r = threadIdx.x; r < BATCH; r += 256)
        acc += g_scnt[r] * logf(g_sexp[r]) - g_sdot[r];
    sm[threadIdx.x] = acc;
    __syncthreads();
    for (int o = 128; o > 0; o >>= 1) {
        if (threadIdx.x < o) sm[threadIdx.x] += sm[threadIdx.x + o];
        __syncthreads();
    }
    if (threadIdx.x == 0) {
        out[0] = sm[0] / (float)BATCH;
        out[1] = -0.5f * g_kl / (float)BATCH;
    }
}

extern "C" void kernel_launch(void* const* d_in, const int* in_sizes, int n_in,
                              void* d_out, int out_size) {
    const float* graph_vals = (const float*)d_in[0];
    const float* Wq         = (const float*)d_in[1];
    const float* bq         = (const float*)d_in[2];
    const float* Wp         = (const float*)d_in[3];
    const float* bp         = (const float*)d_in[4];
    const float* x          = (const float*)d_in[5];
    const float* eps        = (const float*)d_in[6];
    const int*   graph_rows = (const int*)d_in[7];
    const int*   graph_cols = (const int*)d_in[8];
    const int*   user       = (const int*)d_in[9];
    float* out = (float*)d_out;

    k_prep<<<6763, 256>>>(Wq, Wp, user);
    k_edges<<<(NNZ + 255) / 256, 256>>>(graph_vals, graph_rows, graph_cols, user);
    k_z<<<BATCH, 64>>>(bq, eps, user);
    {
        dim3 grid((NUM_ITEMS + 127) / 128, BATCH / 128);
        k_gemm<<<grid, 256>>>(bp, x);
    }
    k_final<<<1, 256>>>(out);
}